// round 2
// baseline (speedup 1.0000x reference)
#include <cuda_runtime.h>

#define BM 128
#define BN 128
#define BK 8
#define TM 8
#define TN 8

// ---------------- scratch (device globals; no allocation allowed) ------------
__device__ float g_k  [16LL * 1024 * 512];   //  33.5 MB
__device__ float g_v  [16LL * 1024 * 512];   //  33.5 MB
__device__ float g_q  [16LL * 2048 * 512];   //  67 MB
__device__ float g_att[16LL * 2048 * 1024];  // 134 MB
__device__ float g_val[16LL * 2048 * 512];   //  67 MB
__device__ int   g_len[16];

// -------- lengths dtype sniffing: reference says int64 but JAX x64 is off ----
// Valid lengths are in [1, 1024]. If the buffer is really int32, reading it as
// int64 packs two entries: lo + hi*2^32 with hi>=1  =>  value > 1024. So
// "all of the first 8 int64 reads in [1,1024]" discriminates perfectly.
// (First 64 bytes are in-bounds under BOTH interpretations.)
__global__ void normalize_lengths(const void* __restrict__ lp)
{
    const long long* l8 = (const long long*)lp;
    const int*       l4 = (const int*)lp;
    bool ok64 = true;
    #pragma unroll
    for (int i = 0; i < 8; ++i) {
        long long v = l8[i];
        if (v < 1 || v > 1024) ok64 = false;
    }
    if (ok64) {
        #pragma unroll
        for (int i = 0; i < 16; ++i) g_len[i] = (int)l8[i];
    } else {
        #pragma unroll
        for (int i = 0; i < 16; ++i) g_len[i] = l4[i];
    }
}

// ---------------- generic row-major SGEMM: C = A@B (+bias), batched ----------
__global__ __launch_bounds__(256) void gemm_rm(
    const float* __restrict__ A, const float* __restrict__ B,
    const float* __restrict__ bias, float* __restrict__ C,
    int M, int N, int K, long long sA, long long sB, long long sC)
{
    A += (long long)blockIdx.z * sA;
    B += (long long)blockIdx.z * sB;
    C += (long long)blockIdx.z * sC;
    const int tid = threadIdx.x;
    const int tx = tid & 15, ty = tid >> 4;
    const int r0 = blockIdx.y * BM, c0 = blockIdx.x * BN;
    __shared__ float As[BK][BM];
    __shared__ float Bs[BK][BN];
    float acc[TM][TN] = {};
    const int arow = tid >> 1, akq = (tid & 1) * 4;
    const int bkr  = tid >> 5, bn  = (tid & 31) * 4;
    for (int k0 = 0; k0 < K; k0 += BK) {
        float4 a4 = *(const float4*)(A + (long long)(r0 + arow) * K + k0 + akq);
        As[akq + 0][arow] = a4.x; As[akq + 1][arow] = a4.y;
        As[akq + 2][arow] = a4.z; As[akq + 3][arow] = a4.w;
        *(float4*)&Bs[bkr][bn] =
            *(const float4*)(B + (long long)(k0 + bkr) * N + c0 + bn);
        __syncthreads();
        #pragma unroll
        for (int k = 0; k < BK; ++k) {
            float a[TM], b[TN];
            #pragma unroll
            for (int i = 0; i < TM; ++i) a[i] = As[k][ty * TM + i];
            #pragma unroll
            for (int j = 0; j < TN; ++j) b[j] = Bs[k][tx * TN + j];
            #pragma unroll
            for (int i = 0; i < TM; ++i)
                #pragma unroll
                for (int j = 0; j < TN; ++j)
                    acc[i][j] += a[i] * b[j];
        }
        __syncthreads();
    }
    #pragma unroll
    for (int i = 0; i < TM; ++i) {
        int r = r0 + ty * TM + i;
        #pragma unroll
        for (int j = 0; j < TN; j += 4) {
            int c = c0 + tx * TN + j;
            float4 o;
            o.x = acc[i][j + 0]; o.y = acc[i][j + 1];
            o.z = acc[i][j + 2]; o.w = acc[i][j + 3];
            if (bias) { o.x += bias[c]; o.y += bias[c + 1];
                        o.z += bias[c + 2]; o.w += bias[c + 3]; }
            *(float4*)(C + (long long)r * N + c) = o;
        }
    }
}

// -------- AᵀB SGEMM for Q: A[row,k] = Ag[k*ldt + row] (g is t-contiguous) ----
__global__ __launch_bounds__(256) void gemm_atb(
    const float* __restrict__ A, const float* __restrict__ B,
    const float* __restrict__ bias, float* __restrict__ C,
    int M, int N, int K, int ldt, long long sA, long long sC)
{
    A += (long long)blockIdx.z * sA;
    C += (long long)blockIdx.z * sC;
    const int tid = threadIdx.x;
    const int tx = tid & 15, ty = tid >> 4;
    const int r0 = blockIdx.y * BM, c0 = blockIdx.x * BN;
    __shared__ float As[BK][BM];
    __shared__ float Bs[BK][BN];
    float acc[TM][TN] = {};
    const int ak = tid >> 5, at = (tid & 31) * 4;
    const int bkr = tid >> 5, bn = (tid & 31) * 4;
    for (int k0 = 0; k0 < K; k0 += BK) {
        *(float4*)&As[ak][at] =
            *(const float4*)(A + (long long)(k0 + ak) * ldt + r0 + at);
        *(float4*)&Bs[bkr][bn] =
            *(const float4*)(B + (long long)(k0 + bkr) * N + c0 + bn);
        __syncthreads();
        #pragma unroll
        for (int k = 0; k < BK; ++k) {
            float a[TM], b[TN];
            #pragma unroll
            for (int i = 0; i < TM; ++i) a[i] = As[k][ty * TM + i];
            #pragma unroll
            for (int j = 0; j < TN; ++j) b[j] = Bs[k][tx * TN + j];
            #pragma unroll
            for (int i = 0; i < TM; ++i)
                #pragma unroll
                for (int j = 0; j < TN; ++j)
                    acc[i][j] += a[i] * b[j];
        }
        __syncthreads();
    }
    #pragma unroll
    for (int i = 0; i < TM; ++i) {
        int r = r0 + ty * TM + i;
        #pragma unroll
        for (int j = 0; j < TN; j += 4) {
            int c = c0 + tx * TN + j;
            float4 o;
            o.x = acc[i][j + 0] + bias[c];     o.y = acc[i][j + 1] + bias[c + 1];
            o.z = acc[i][j + 2] + bias[c + 2]; o.w = acc[i][j + 3] + bias[c + 3];
            *(float4*)(C + (long long)r * N + c) = o;
        }
    }
}

// -------- ABᵀ SGEMM for scores: C[t,s] = scale * q[t,:]·k[s,:] ---------------
__global__ __launch_bounds__(256) void gemm_abt(
    const float* __restrict__ A, const float* __restrict__ Bm,
    float* __restrict__ C, int M, int N, int K,
    long long sA, long long sB, long long sC, float scale)
{
    A  += (long long)blockIdx.z * sA;
    Bm += (long long)blockIdx.z * sB;
    C  += (long long)blockIdx.z * sC;
    const int tid = threadIdx.x;
    const int tx = tid & 15, ty = tid >> 4;
    const int r0 = blockIdx.y * BM, c0 = blockIdx.x * BN;
    __shared__ float As[BK][BM];
    __shared__ float Bs[BK][BN];
    float acc[TM][TN] = {};
    const int arow = tid >> 1, akq = (tid & 1) * 4;
    const int brow = tid >> 1, bkq = (tid & 1) * 4;
    for (int k0 = 0; k0 < K; k0 += BK) {
        float4 a4 = *(const float4*)(A + (long long)(r0 + arow) * K + k0 + akq);
        As[akq + 0][arow] = a4.x; As[akq + 1][arow] = a4.y;
        As[akq + 2][arow] = a4.z; As[akq + 3][arow] = a4.w;
        float4 b4 = *(const float4*)(Bm + (long long)(c0 + brow) * K + k0 + bkq);
        Bs[bkq + 0][brow] = b4.x; Bs[bkq + 1][brow] = b4.y;
        Bs[bkq + 2][brow] = b4.z; Bs[bkq + 3][brow] = b4.w;
        __syncthreads();
        #pragma unroll
        for (int k = 0; k < BK; ++k) {
            float a[TM], b[TN];
            #pragma unroll
            for (int i = 0; i < TM; ++i) a[i] = As[k][ty * TM + i];
            #pragma unroll
            for (int j = 0; j < TN; ++j) b[j] = Bs[k][tx * TN + j];
            #pragma unroll
            for (int i = 0; i < TM; ++i)
                #pragma unroll
                for (int j = 0; j < TN; ++j)
                    acc[i][j] += a[i] * b[j];
        }
        __syncthreads();
    }
    #pragma unroll
    for (int i = 0; i < TM; ++i) {
        int r = r0 + ty * TM + i;
        #pragma unroll
        for (int j = 0; j < TN; j += 4) {
            int c = c0 + tx * TN + j;
            float4 o;
            o.x = acc[i][j + 0] * scale; o.y = acc[i][j + 1] * scale;
            o.z = acc[i][j + 2] * scale; o.w = acc[i][j + 3] * scale;
            *(float4*)(C + (long long)r * N + c) = o;
        }
    }
}

// -------- mel GEMM with fused [B,T,20,64] -> [B,64,20,T] permute -------------
__global__ __launch_bounds__(256) void gemm_mel(
    const float* __restrict__ A, const float* __restrict__ B,
    const float* __restrict__ bias, float* __restrict__ out)
{
    const int N = 1280, K = 512;
    const int tid = threadIdx.x;
    const int tx = tid & 15, ty = tid >> 4;
    const int r0 = blockIdx.y * BM, c0 = blockIdx.x * BN;
    __shared__ float As[BK][BM];
    __shared__ float Bs[BK][BN];
    float acc[TM][TN] = {};
    const int arow = tid >> 1, akq = (tid & 1) * 4;
    const int bkr  = tid >> 5, bn  = (tid & 31) * 4;
    for (int k0 = 0; k0 < K; k0 += BK) {
        float4 a4 = *(const float4*)(A + (long long)(r0 + arow) * K + k0 + akq);
        As[akq + 0][arow] = a4.x; As[akq + 1][arow] = a4.y;
        As[akq + 2][arow] = a4.z; As[akq + 3][arow] = a4.w;
        *(float4*)&Bs[bkr][bn] =
            *(const float4*)(B + (long long)(k0 + bkr) * N + c0 + bn);
        __syncthreads();
        #pragma unroll
        for (int k = 0; k < BK; ++k) {
            float a[TM], b[TN];
            #pragma unroll
            for (int i = 0; i < TM; ++i) a[i] = As[k][ty * TM + i];
            #pragma unroll
            for (int j = 0; j < TN; ++j) b[j] = Bs[k][tx * TN + j];
            #pragma unroll
            for (int i = 0; i < TM; ++i)
                #pragma unroll
                for (int j = 0; j < TN; ++j)
                    acc[i][j] += a[i] * b[j];
        }
        __syncthreads();
    }
    // rows = global (b*2048 + t); a 128-row block never crosses a batch bound.
    const int rbase = r0 + ty * TM;
    const int b  = rbase >> 11;
    const int t  = rbase & 2047;            // multiple of 8 -> float4-aligned
    #pragma unroll
    for (int j = 0; j < TN; ++j) {
        int col = c0 + tx * TN + j;         // mel index m = f*64 + x
        int f = col >> 6, x = col & 63;
        float bb = bias[col];
        float* o = out + (((long long)(b * 64 + x) * 20 + f) * 2048) + t;
        float4 v0, v1;
        v0.x = acc[0][j] + bb; v0.y = acc[1][j] + bb;
        v0.z = acc[2][j] + bb; v0.w = acc[3][j] + bb;
        v1.x = acc[4][j] + bb; v1.y = acc[5][j] + bb;
        v1.z = acc[6][j] + bb; v1.w = acc[7][j] + bb;
        *(float4*)(o)     = v0;
        *(float4*)(o + 4) = v1;
    }
}

// -------- masked softmax over S=1024 per (b,t) row ---------------------------
__global__ __launch_bounds__(256) void softmax_rows(float* __restrict__ att)
{
    const int row = blockIdx.x;
    const int b = row >> 11;
    float* p = att + (long long)row * 1024;
    const int len = g_len[b];
    const int tid = threadIdx.x;
    const int s0 = tid * 4;
    float4 v = ((const float4*)p)[tid];
    float vals[4] = {v.x, v.y, v.z, v.w};
    float mx = -1e30f;
    #pragma unroll
    for (int u = 0; u < 4; ++u)
        if (s0 + u < len && vals[u] > mx) mx = vals[u];
    __shared__ float red[8];
    #pragma unroll
    for (int off = 16; off > 0; off >>= 1)
        mx = fmaxf(mx, __shfl_xor_sync(0xffffffffu, mx, off));
    if ((tid & 31) == 0) red[tid >> 5] = mx;
    __syncthreads();
    mx = red[0];
    #pragma unroll
    for (int i = 1; i < 8; ++i) mx = fmaxf(mx, red[i]);
    __syncthreads();
    float sum = 0.f;
    #pragma unroll
    for (int u = 0; u < 4; ++u) {
        float e = (s0 + u < len) ? __expf(vals[u] - mx) : 0.f;
        vals[u] = e; sum += e;
    }
    #pragma unroll
    for (int off = 16; off > 0; off >>= 1)
        sum += __shfl_xor_sync(0xffffffffu, sum, off);
    if ((tid & 31) == 0) red[tid >> 5] = sum;
    __syncthreads();
    sum = 0.f;
    #pragma unroll
    for (int i = 0; i < 8; ++i) sum += red[i];
    const float inv = 1.f / sum;
    v.x = vals[0] * inv; v.y = vals[1] * inv;
    v.z = vals[2] * inv; v.w = vals[3] * inv;
    ((float4*)p)[tid] = v;
}

// ---------------------------------------------------------------------------
extern "C" void kernel_launch(void* const* d_in, const int* in_sizes, int n_in,
                              void* d_out, int out_size)
{
    const float* ph      = (const float*)d_in[0];   // [16,1024,512]
    const float* g       = (const float*)d_in[1];   // [16,128,20,2048]
    const void*  lengths = d_in[2];                 // int32 or int64 -> sniffed
    const float* Wk      = (const float*)d_in[3];
    const float* bk      = (const float*)d_in[4];
    const float* Wv      = (const float*)d_in[5];
    const float* bv      = (const float*)d_in[6];
    const float* Wq      = (const float*)d_in[7];
    const float* bq      = (const float*)d_in[8];
    const float* Wmel    = (const float*)d_in[9];
    const float* bmel    = (const float*)d_in[10];
    float* out = (float*)d_out;

    float *k_, *v_, *q_, *att_, *val_;
    cudaGetSymbolAddress((void**)&k_,   g_k);
    cudaGetSymbolAddress((void**)&v_,   g_v);
    cudaGetSymbolAddress((void**)&q_,   g_q);
    cudaGetSymbolAddress((void**)&att_, g_att);
    cudaGetSymbolAddress((void**)&val_, g_val);

    const dim3 th(256);

    normalize_lengths<<<1, 1>>>(lengths);

    // k = ph@Wk + bk ; v = ph@Wv + bv   (M=16384, N=512, K=512)
    gemm_rm<<<dim3(4, 128, 1), th>>>(ph, Wk, bk, k_, 16384, 512, 512, 0, 0, 0);
    gemm_rm<<<dim3(4, 128, 1), th>>>(ph, Wv, bv, v_, 16384, 512, 512, 0, 0, 0);

    // q = g^T @ Wq + bq   (per batch: M=2048, N=512, K=2560; A t-contiguous)
    gemm_atb<<<dim3(4, 16, 16), th>>>(g, Wq, bq, q_, 2048, 512, 2560, 2048,
                                      2560LL * 2048, 2048LL * 512);

    // att = (q k^T) / sqrt(512)   (per batch: M=2048, N=1024, K=512)
    gemm_abt<<<dim3(8, 16, 16), th>>>(q_, k_, att_, 2048, 1024, 512,
                                      2048LL * 512, 1024LL * 512, 2048LL * 1024,
                                      0.04419417382415922f);

    // masked softmax over S per row
    softmax_rows<<<32768, 256>>>(att_);

    // value = att @ v   (per batch: M=2048, N=512, K=1024)
    gemm_rm<<<dim3(4, 16, 16), th>>>(att_, v_, nullptr, val_, 2048, 512, 1024,
                                     2048LL * 1024, 1024LL * 512, 2048LL * 512);

    // out = permute(value @ Wmel + bmel)   (M=32768, N=1280, K=512)
    gemm_mel<<<dim3(10, 256, 1), th>>>(val_, Wmel, bmel, out);
}

// round 5
// speedup vs baseline: 2.4213x; 2.4213x over previous
#include <cuda_runtime.h>
#include <cstdint>

// ---------------- scratch (device globals; no allocation allowed) ------------
__device__ float g_k  [16LL * 1024 * 512];   //  33.5 MB
__device__ float g_v  [16LL * 1024 * 512];   //  33.5 MB
__device__ float g_q  [16LL * 2048 * 512];   //  67 MB
__device__ float g_att[16LL * 2048 * 1024];  // 134 MB
__device__ float g_val[16LL * 2048 * 512];   //  67 MB
__device__ int   g_len[16];

// -------- lengths dtype sniffing (reference says int64; JAX x64-off -> int32)
__global__ void normalize_lengths(const void* __restrict__ lp)
{
    const long long* l8 = (const long long*)lp;
    const int*       l4 = (const int*)lp;
    bool ok64 = true;
    for (int i = 0; i < 8; ++i) {
        long long v = l8[i];
        if (v < 1 || v > 1024) ok64 = false;
    }
    if (ok64) {
        for (int i = 0; i < 16; ++i) g_len[i] = (int)l8[i];
    } else {
        for (int i = 0; i < 16; ++i) g_len[i] = l4[i];
    }
}

// ---------------------------------------------------------------------------
// tf32 helpers
__device__ __forceinline__ unsigned f2tf(float x) {
    unsigned u;
    asm("cvt.rna.tf32.f32 %0, %1;" : "=r"(u) : "f"(x));
    return u;
}

__device__ __forceinline__ void mma8(float* c, const unsigned* a,
                                     unsigned b0, unsigned b1) {
    asm volatile(
        "mma.sync.aligned.m16n8k8.row.col.f32.tf32.tf32.f32 "
        "{%0,%1,%2,%3},{%4,%5,%6,%7},{%8,%9},{%0,%1,%2,%3};"
        : "+f"(c[0]), "+f"(c[1]), "+f"(c[2]), "+f"(c[3])
        : "r"(a[0]), "r"(a[1]), "r"(a[2]), "r"(a[3]), "r"(b0), "r"(b1));
}

// ---------------------------------------------------------------------------
// Unified tf32 tensor-core GEMM, 128x128x16 tiles, 256 threads (8 warps 2m x 4n),
// warp tile 64x32, m16n8k8. Double-buffered smem, LDG prefetch.
//
// AT=0: A row-major [M,K]  (m rows, k contig)  -> smem As[m][20]
// AT=1: A k-major  [K,M]   (k rows, m contig)  -> smem As[k][136]
// BT=0: B [K,N]            (k rows, n contig)  -> smem Bs[k][136]
// BT=1: B^T [N,K]          (n rows, k contig)  -> smem Bs[n][20]
// EPI=0: C = alpha*(A@B) + bias[col] (bias optional), row-major ldc
// EPI=2: mel permute: rows are mel indices, cols are t
template<int AT, int BT, int EPI>
__global__ __launch_bounds__(256, 1) void tc_gemm(
    const float* __restrict__ A, const float* __restrict__ Bm,
    const float* __restrict__ bias, float* __restrict__ C,
    int K, int lda, int ldb, int ldc,
    long long sA, long long sB, long long sC, float alpha)
{
    constexpr int ASZ = AT ? 16 * 136 : 128 * 20;
    constexpr int BSZ = BT ? 128 * 20 : 16 * 136;
    __shared__ unsigned smA[2][ASZ];
    __shared__ unsigned smB[2][BSZ];

    A  += blockIdx.z * sA;
    Bm += blockIdx.z * sB;
    const int tid  = threadIdx.x;
    const int lane = tid & 31, warp = tid >> 5;
    const int g  = lane >> 2, tg = lane & 3;
    const int wm = warp & 1,  wn = warp >> 1;
    const int r0 = blockIdx.y * 128, c0 = blockIdx.x * 128;

    const float* aptr[2]; unsigned adst[2];
    const float* bptr[2]; unsigned bdst[2];
    #pragma unroll
    for (int r = 0; r < 2; ++r) {
        int i = tid + 256 * r;
        if (!AT) { int m = i >> 2, kq = (i & 3) * 4;
                   aptr[r] = A + (long long)(r0 + m) * lda + kq;
                   adst[r] = m * 20 + kq; }
        else     { int k = i >> 5, m4 = (i & 31) * 4;
                   aptr[r] = A + (long long)k * lda + r0 + m4;
                   adst[r] = k * 136 + m4; }
        if (!BT) { int k = i >> 5, n4 = (i & 31) * 4;
                   bptr[r] = Bm + (long long)k * ldb + c0 + n4;
                   bdst[r] = k * 136 + n4; }
        else     { int n = i >> 2, kq = (i & 3) * 4;
                   bptr[r] = Bm + (long long)(c0 + n) * ldb + kq;
                   bdst[r] = n * 20 + kq; }
    }
    const long long adv_a = AT ? 16LL * lda : 16LL;
    const long long adv_b = BT ? 16LL : 16LL * ldb;

    float acc[4][4][4] = {};
    const int nIter = K >> 4;

    float4 pa[2], pb[2];
    #pragma unroll
    for (int r = 0; r < 2; ++r) {
        pa[r] = *(const float4*)aptr[r];
        pb[r] = *(const float4*)bptr[r];
    }

    int buf = 0;
    for (int it = 0; it < nIter; ++it) {
        #pragma unroll
        for (int r = 0; r < 2; ++r) {
            uint4 ua; ua.x = f2tf(pa[r].x); ua.y = f2tf(pa[r].y);
                      ua.z = f2tf(pa[r].z); ua.w = f2tf(pa[r].w);
            *(uint4*)&smA[buf][adst[r]] = ua;
            uint4 ub; ub.x = f2tf(pb[r].x); ub.y = f2tf(pb[r].y);
                      ub.z = f2tf(pb[r].z); ub.w = f2tf(pb[r].w);
            *(uint4*)&smB[buf][bdst[r]] = ub;
        }
        __syncthreads();
        if (it + 1 < nIter) {
            #pragma unroll
            for (int r = 0; r < 2; ++r) {
                aptr[r] += adv_a; bptr[r] += adv_b;
                pa[r] = *(const float4*)aptr[r];
                pb[r] = *(const float4*)bptr[r];
            }
        }
        const unsigned* As = smA[buf];
        const unsigned* Bs = smB[buf];
        #pragma unroll
        for (int kk = 0; kk < 16; kk += 8) {
            unsigned af[4][4];
            const int k = kk + tg;
            #pragma unroll
            for (int mi = 0; mi < 4; ++mi) {
                int m = wm * 64 + mi * 16 + g;
                if (!AT) {
                    af[mi][0] = As[m * 20 + k];
                    af[mi][1] = As[(m + 8) * 20 + k];
                    af[mi][2] = As[m * 20 + k + 4];
                    af[mi][3] = As[(m + 8) * 20 + k + 4];
                } else {
                    af[mi][0] = As[k * 136 + m];
                    af[mi][1] = As[k * 136 + m + 8];
                    af[mi][2] = As[(k + 4) * 136 + m];
                    af[mi][3] = As[(k + 4) * 136 + m + 8];
                }
            }
            #pragma unroll
            for (int ni = 0; ni < 4; ++ni) {
                int n = wn * 32 + ni * 8 + g;
                unsigned b0, b1;
                if (!BT) { b0 = Bs[k * 136 + n]; b1 = Bs[(k + 4) * 136 + n]; }
                else     { b0 = Bs[n * 20 + k];  b1 = Bs[n * 20 + k + 4]; }
                #pragma unroll
                for (int mi = 0; mi < 4; ++mi)
                    mma8(acc[mi][ni], af[mi], b0, b1);
            }
        }
        buf ^= 1;
    }

    if (EPI == 2) {
        const int b = blockIdx.z;
        #pragma unroll
        for (int mi = 0; mi < 4; ++mi) {
            int row = r0 + wm * 64 + mi * 16 + g;
            #pragma unroll
            for (int rr = 0; rr < 2; ++rr) {
                int mel = row + rr * 8;
                float bb = bias[mel];
                float* op = C + ((long long)(b * 64 + (mel & 63)) * 20 + (mel >> 6)) * 2048;
                #pragma unroll
                for (int ni = 0; ni < 4; ++ni) {
                    int t = c0 + wn * 32 + ni * 8 + 2 * tg;
                    float2 v;
                    v.x = acc[mi][ni][rr * 2 + 0] + bb;
                    v.y = acc[mi][ni][rr * 2 + 1] + bb;
                    *(float2*)(op + t) = v;
                }
            }
        }
    } else {
        C += blockIdx.z * sC;
        #pragma unroll
        for (int mi = 0; mi < 4; ++mi) {
            int row = r0 + wm * 64 + mi * 16 + g;
            #pragma unroll
            for (int ni = 0; ni < 4; ++ni) {
                int col = c0 + wn * 32 + ni * 8 + 2 * tg;
                float b0v = bias ? bias[col] : 0.f;
                float b1v = bias ? bias[col + 1] : 0.f;
                float2 v0, v1;
                v0.x = alpha * acc[mi][ni][0] + b0v;
                v0.y = alpha * acc[mi][ni][1] + b1v;
                v1.x = alpha * acc[mi][ni][2] + b0v;
                v1.y = alpha * acc[mi][ni][3] + b1v;
                *(float2*)(C + (long long)row * ldc + col)       = v0;
                *(float2*)(C + (long long)(row + 8) * ldc + col) = v1;
            }
        }
    }
}

// -------- masked softmax over S=1024 per (b,t) row ---------------------------
__global__ __launch_bounds__(256) void softmax_rows(float* __restrict__ att)
{
    const int row = blockIdx.x;
    const int b = row >> 11;
    float* p = att + (long long)row * 1024;
    const int len = g_len[b];
    const int tid = threadIdx.x;
    const int s0 = tid * 4;
    float4 v = ((const float4*)p)[tid];
    float vals[4] = {v.x, v.y, v.z, v.w};
    float mx = -1e30f;
    #pragma unroll
    for (int u = 0; u < 4; ++u)
        if (s0 + u < len && vals[u] > mx) mx = vals[u];
    __shared__ float red[8];
    #pragma unroll
    for (int off = 16; off > 0; off >>= 1)
        mx = fmaxf(mx, __shfl_xor_sync(0xffffffffu, mx, off));
    if ((tid & 31) == 0) red[tid >> 5] = mx;
    __syncthreads();
    mx = red[0];
    #pragma unroll
    for (int i = 1; i < 8; ++i) mx = fmaxf(mx, red[i]);
    __syncthreads();
    float sum = 0.f;
    #pragma unroll
    for (int u = 0; u < 4; ++u) {
        float e = (s0 + u < len) ? __expf(vals[u] - mx) : 0.f;
        vals[u] = e; sum += e;
    }
    #pragma unroll
    for (int off = 16; off > 0; off >>= 1)
        sum += __shfl_xor_sync(0xffffffffu, sum, off);
    if ((tid & 31) == 0) red[tid >> 5] = sum;
    __syncthreads();
    sum = 0.f;
    #pragma unroll
    for (int i = 0; i < 8; ++i) sum += red[i];
    const float inv = 1.f / sum;
    v.x = vals[0] * inv; v.y = vals[1] * inv;
    v.z = vals[2] * inv; v.w = vals[3] * inv;
    ((float4*)p)[tid] = v;
}

// ---------------------------------------------------------------------------
extern "C" void kernel_launch(void* const* d_in, const int* in_sizes, int n_in,
                              void* d_out, int out_size)
{
    const float* ph      = (const float*)d_in[0];   // [16,1024,512]
    const float* g       = (const float*)d_in[1];   // [16,2560,2048] (c*f, t)
    const void*  lengths = d_in[2];
    const float* Wk      = (const float*)d_in[3];
    const float* bk      = (const float*)d_in[4];
    const float* Wv      = (const float*)d_in[5];
    const float* bv      = (const float*)d_in[6];
    const float* Wq      = (const float*)d_in[7];
    const float* bq      = (const float*)d_in[8];
    const float* Wmel    = (const float*)d_in[9];
    const float* bmel    = (const float*)d_in[10];
    float* out = (float*)d_out;

    float *k_, *v_, *q_, *att_, *val_;
    cudaGetSymbolAddress((void**)&k_,   g_k);
    cudaGetSymbolAddress((void**)&v_,   g_v);
    cudaGetSymbolAddress((void**)&q_,   g_q);
    cudaGetSymbolAddress((void**)&att_, g_att);
    cudaGetSymbolAddress((void**)&val_, g_val);

    const dim3 th(256);

    normalize_lengths<<<1, 1>>>(lengths);

    // k = ph@Wk + bk ; v = ph@Wv + bv   (A rm [16384,512], B [512,512])
    tc_gemm<0,0,0><<<dim3(4, 128, 1), th>>>(ph, Wk, bk, k_,
        512, 512, 512, 512, 0, 0, 0, 1.f);
    tc_gemm<0,0,0><<<dim3(4, 128, 1), th>>>(ph, Wv, bv, v_,
        512, 512, 512, 512, 0, 0, 0, 1.f);

    // q = g^T@Wq + bq  (A k-major [2560,2048] per batch, B [2560,512])
    tc_gemm<1,0,0><<<dim3(4, 16, 16), th>>>(g, Wq, bq, q_,
        2560, 2048, 512, 512, 2560LL * 2048, 0, 2048LL * 512, 1.f);

    // att = scale * q@k^T  (A rm [2048,512], B^T [1024,512] per batch)
    tc_gemm<0,1,0><<<dim3(8, 16, 16), th>>>(q_, k_, nullptr, att_,
        512, 512, 512, 1024, 2048LL * 512, 1024LL * 512, 2048LL * 1024,
        0.04419417382415922f);

    softmax_rows<<<32768, 256>>>(att_);

    // value = att@v  (A rm [2048,1024], B [1024,512] per batch)
    tc_gemm<0,0,0><<<dim3(4, 16, 16), th>>>(att_, v_, nullptr, val_,
        1024, 1024, 512, 512, 2048LL * 1024, 1024LL * 512, 2048LL * 512, 1.f);

    // out^T = Wmel^T @ val^T + bmel, with fused permute
    // (A k-major [512,1280] shared, B^T = val [2048,512] per batch, cols = t)
    tc_gemm<1,1,2><<<dim3(16, 10, 16), th>>>(Wmel, val_, bmel, out,
        512, 1280, 512, 2048, 0, 2048LL * 512, 0, 1.f);
}

// round 6
// speedup vs baseline: 3.3317x; 1.3760x over previous
#include <cuda_runtime.h>
#include <cstdint>

// ---------------- scratch (device globals; no allocation allowed) ------------
__device__ float g_k  [16LL * 1024 * 512];   //  33.5 MB
__device__ float g_v  [16LL * 1024 * 512];   //  33.5 MB
__device__ float g_q  [16LL * 2048 * 512];   //  67 MB
__device__ float g_att[16LL * 2048 * 1024];  // 134 MB
__device__ float g_val[16LL * 2048 * 512];   //  67 MB
__device__ int   g_len[16];

// -------- lengths dtype sniffing (reference says int64; JAX x64-off -> int32)
__global__ void normalize_lengths(const void* __restrict__ lp)
{
    const long long* l8 = (const long long*)lp;
    const int*       l4 = (const int*)lp;
    bool ok64 = true;
    for (int i = 0; i < 8; ++i) {
        long long v = l8[i];
        if (v < 1 || v > 1024) ok64 = false;
    }
    if (ok64) {
        for (int i = 0; i < 16; ++i) g_len[i] = (int)l8[i];
    } else {
        for (int i = 0; i < 16; ++i) g_len[i] = l4[i];
    }
}

// ---------------------------------------------------------------------------
// tf32 helpers
__device__ __forceinline__ unsigned f2tf(float x) {
    unsigned u;
    asm("cvt.rna.tf32.f32 %0, %1;" : "=r"(u) : "f"(x));
    return u;
}

__device__ __forceinline__ void mma8(float* c, const unsigned* a,
                                     unsigned b0, unsigned b1) {
    asm volatile(
        "mma.sync.aligned.m16n8k8.row.col.f32.tf32.tf32.f32 "
        "{%0,%1,%2,%3},{%4,%5,%6,%7},{%8,%9},{%0,%1,%2,%3};"
        : "+f"(c[0]), "+f"(c[1]), "+f"(c[2]), "+f"(c[3])
        : "r"(a[0]), "r"(a[1]), "r"(a[2]), "r"(a[3]), "r"(b0), "r"(b1));
}

// ---------------------------------------------------------------------------
// Unified tf32 tensor-core GEMM, 128x128x16 tiles, 256 threads (8 warps 2m x 4n),
// warp tile 64x32, m16n8k8. Double-buffered smem, LDG prefetch, 2 CTAs/SM.
//
// AT=0: A row-major [M,K]  (m rows, k contig)  -> smem As[m][20]
// AT=1: A k-major  [K,M]   (k rows, m contig)  -> smem As[k][136]
// BT=0: B [K,N]            (k rows, n contig)  -> smem Bs[k][136]
// BT=1: B^T [N,K]          (n rows, k contig)  -> smem Bs[n][20]
// EPI=0: C = alpha*(A@B) + bias[col] (bias optional), row-major ldc
// EPI=2: mel permute: rows are mel indices, cols are t
template<int AT, int BT, int EPI>
__global__ __launch_bounds__(256, 2) void tc_gemm(
    const float* __restrict__ A, const float* __restrict__ Bm,
    const float* __restrict__ bias, float* __restrict__ C,
    int K, int lda, int ldb, int ldc,
    long long sA, long long sB, long long sC, float alpha)
{
    constexpr int ASZ = AT ? 16 * 136 : 128 * 20;
    constexpr int BSZ = BT ? 128 * 20 : 16 * 136;
    __shared__ unsigned smA[2][ASZ];
    __shared__ unsigned smB[2][BSZ];

    A  += blockIdx.z * sA;
    Bm += blockIdx.z * sB;
    const int tid  = threadIdx.x;
    const int lane = tid & 31, warp = tid >> 5;
    const int g  = lane >> 2, tg = lane & 3;
    const int wm = warp & 1,  wn = warp >> 1;
    const int r0 = blockIdx.y * 128, c0 = blockIdx.x * 128;

    const float* aptr[2]; unsigned adst[2];
    const float* bptr[2]; unsigned bdst[2];
    #pragma unroll
    for (int r = 0; r < 2; ++r) {
        int i = tid + 256 * r;
        if (!AT) { int m = i >> 2, kq = (i & 3) * 4;
                   aptr[r] = A + (long long)(r0 + m) * lda + kq;
                   adst[r] = m * 20 + kq; }
        else     { int k = i >> 5, m4 = (i & 31) * 4;
                   aptr[r] = A + (long long)k * lda + r0 + m4;
                   adst[r] = k * 136 + m4; }
        if (!BT) { int k = i >> 5, n4 = (i & 31) * 4;
                   bptr[r] = Bm + (long long)k * ldb + c0 + n4;
                   bdst[r] = k * 136 + n4; }
        else     { int n = i >> 2, kq = (i & 3) * 4;
                   bptr[r] = Bm + (long long)(c0 + n) * ldb + kq;
                   bdst[r] = n * 20 + kq; }
    }
    const long long adv_a = AT ? 16LL * lda : 16LL;
    const long long adv_b = BT ? 16LL : 16LL * ldb;

    float acc[4][4][4] = {};
    const int nIter = K >> 4;

    float4 pa[2], pb[2];
    #pragma unroll
    for (int r = 0; r < 2; ++r) {
        pa[r] = *(const float4*)aptr[r];
        pb[r] = *(const float4*)bptr[r];
    }

    int buf = 0;
    for (int it = 0; it < nIter; ++it) {
        #pragma unroll
        for (int r = 0; r < 2; ++r) {
            uint4 ua; ua.x = f2tf(pa[r].x); ua.y = f2tf(pa[r].y);
                      ua.z = f2tf(pa[r].z); ua.w = f2tf(pa[r].w);
            *(uint4*)&smA[buf][adst[r]] = ua;
            uint4 ub; ub.x = f2tf(pb[r].x); ub.y = f2tf(pb[r].y);
                      ub.z = f2tf(pb[r].z); ub.w = f2tf(pb[r].w);
            *(uint4*)&smB[buf][bdst[r]] = ub;
        }
        __syncthreads();
        if (it + 1 < nIter) {
            #pragma unroll
            for (int r = 0; r < 2; ++r) {
                aptr[r] += adv_a; bptr[r] += adv_b;
                pa[r] = *(const float4*)aptr[r];
                pb[r] = *(const float4*)bptr[r];
            }
        }
        const unsigned* As = smA[buf];
        const unsigned* Bs = smB[buf];
        #pragma unroll
        for (int kk = 0; kk < 16; kk += 8) {
            unsigned af[4][4];
            const int k = kk + tg;
            #pragma unroll
            for (int mi = 0; mi < 4; ++mi) {
                int m = wm * 64 + mi * 16 + g;
                if (!AT) {
                    af[mi][0] = As[m * 20 + k];
                    af[mi][1] = As[(m + 8) * 20 + k];
                    af[mi][2] = As[m * 20 + k + 4];
                    af[mi][3] = As[(m + 8) * 20 + k + 4];
                } else {
                    af[mi][0] = As[k * 136 + m];
                    af[mi][1] = As[k * 136 + m + 8];
                    af[mi][2] = As[(k + 4) * 136 + m];
                    af[mi][3] = As[(k + 4) * 136 + m + 8];
                }
            }
            #pragma unroll
            for (int ni = 0; ni < 4; ++ni) {
                int n = wn * 32 + ni * 8 + g;
                unsigned b0, b1;
                if (!BT) { b0 = Bs[k * 136 + n]; b1 = Bs[(k + 4) * 136 + n]; }
                else     { b0 = Bs[n * 20 + k];  b1 = Bs[n * 20 + k + 4]; }
                #pragma unroll
                for (int mi = 0; mi < 4; ++mi)
                    mma8(acc[mi][ni], af[mi], b0, b1);
            }
        }
        buf ^= 1;
    }

    if (EPI == 2) {
        const int b = blockIdx.z;
        #pragma unroll
        for (int mi = 0; mi < 4; ++mi) {
            int row = r0 + wm * 64 + mi * 16 + g;
            #pragma unroll
            for (int rr = 0; rr < 2; ++rr) {
                int mel = row + rr * 8;
                float bb = bias[mel];
                float* op = C + ((long long)(b * 64 + (mel & 63)) * 20 + (mel >> 6)) * 2048;
                #pragma unroll
                for (int ni = 0; ni < 4; ++ni) {
                    int t = c0 + wn * 32 + ni * 8 + 2 * tg;
                    float2 v;
                    v.x = acc[mi][ni][rr * 2 + 0] + bb;
                    v.y = acc[mi][ni][rr * 2 + 1] + bb;
                    *(float2*)(op + t) = v;
                }
            }
        }
    } else {
        C += blockIdx.z * sC;
        #pragma unroll
        for (int mi = 0; mi < 4; ++mi) {
            int row = r0 + wm * 64 + mi * 16 + g;
            #pragma unroll
            for (int ni = 0; ni < 4; ++ni) {
                int col = c0 + wn * 32 + ni * 8 + 2 * tg;
                float b0v = bias ? bias[col] : 0.f;
                float b1v = bias ? bias[col + 1] : 0.f;
                float2 v0, v1;
                v0.x = alpha * acc[mi][ni][0] + b0v;
                v0.y = alpha * acc[mi][ni][1] + b1v;
                v1.x = alpha * acc[mi][ni][2] + b0v;
                v1.y = alpha * acc[mi][ni][3] + b1v;
                *(float2*)(C + (long long)row * ldc + col)       = v0;
                *(float2*)(C + (long long)(row + 8) * ldc + col) = v1;
            }
        }
    }
}

// -------- masked softmax over S=1024 per (b,t) row ---------------------------
__global__ __launch_bounds__(256) void softmax_rows(float* __restrict__ att)
{
    const int row = blockIdx.x;
    const int b = row >> 11;
    float* p = att + (long long)row * 1024;
    const int len = g_len[b];
    const int tid = threadIdx.x;
    const int s0 = tid * 4;
    float4 v = ((const float4*)p)[tid];
    float vals[4] = {v.x, v.y, v.z, v.w};
    float mx = -1e30f;
    #pragma unroll
    for (int u = 0; u < 4; ++u)
        if (s0 + u < len && vals[u] > mx) mx = vals[u];
    __shared__ float red[8];
    #pragma unroll
    for (int off = 16; off > 0; off >>= 1)
        mx = fmaxf(mx, __shfl_xor_sync(0xffffffffu, mx, off));
    if ((tid & 31) == 0) red[tid >> 5] = mx;
    __syncthreads();
    mx = red[0];
    #pragma unroll
    for (int i = 1; i < 8; ++i) mx = fmaxf(mx, red[i]);
    __syncthreads();
    float sum = 0.f;
    #pragma unroll
    for (int u = 0; u < 4; ++u) {
        float e = (s0 + u < len) ? __expf(vals[u] - mx) : 0.f;
        vals[u] = e; sum += e;
    }
    #pragma unroll
    for (int off = 16; off > 0; off >>= 1)
        sum += __shfl_xor_sync(0xffffffffu, sum, off);
    if ((tid & 31) == 0) red[tid >> 5] = sum;
    __syncthreads();
    sum = 0.f;
    #pragma unroll
    for (int i = 0; i < 8; ++i) sum += red[i];
    const float inv = 1.f / sum;
    v.x = vals[0] * inv; v.y = vals[1] * inv;
    v.z = vals[2] * inv; v.w = vals[3] * inv;
    ((float4*)p)[tid] = v;
}

// ---------------------------------------------------------------------------
extern "C" void kernel_launch(void* const* d_in, const int* in_sizes, int n_in,
                              void* d_out, int out_size)
{
    const float* ph      = (const float*)d_in[0];   // [16,1024,512]
    const float* g       = (const float*)d_in[1];   // [16,2560,2048] (c*f, t)
    const void*  lengths = d_in[2];
    const float* Wk      = (const float*)d_in[3];
    const float* bk      = (const float*)d_in[4];
    const float* Wv      = (const float*)d_in[5];
    const float* bv      = (const float*)d_in[6];
    const float* Wq      = (const float*)d_in[7];
    const float* bq      = (const float*)d_in[8];
    const float* Wmel    = (const float*)d_in[9];
    const float* bmel    = (const float*)d_in[10];
    float* out = (float*)d_out;

    float *k_, *v_, *q_, *att_, *val_;
    cudaGetSymbolAddress((void**)&k_,   g_k);
    cudaGetSymbolAddress((void**)&v_,   g_v);
    cudaGetSymbolAddress((void**)&q_,   g_q);
    cudaGetSymbolAddress((void**)&att_, g_att);
    cudaGetSymbolAddress((void**)&val_, g_val);

    const dim3 th(256);

    normalize_lengths<<<1, 1>>>(lengths);

    // k = ph@Wk + bk ; v = ph@Wv + bv   (A rm [16384,512], B [512,512])
    tc_gemm<0,0,0><<<dim3(4, 128, 1), th>>>(ph, Wk, bk, k_,
        512, 512, 512, 512, 0, 0, 0, 1.f);
    tc_gemm<0,0,0><<<dim3(4, 128, 1), th>>>(ph, Wv, bv, v_,
        512, 512, 512, 512, 0, 0, 0, 1.f);

    // q = g^T@Wq + bq  (A k-major [2560,2048] per batch, B [2560,512])
    tc_gemm<1,0,0><<<dim3(4, 16, 16), th>>>(g, Wq, bq, q_,
        2560, 2048, 512, 512, 2560LL * 2048, 0, 2048LL * 512, 1.f);

    // att = scale * q@k^T  (A rm [2048,512], B^T [1024,512] per batch)
    tc_gemm<0,1,0><<<dim3(8, 16, 16), th>>>(q_, k_, nullptr, att_,
        512, 512, 512, 1024, 2048LL * 512, 1024LL * 512, 2048LL * 1024,
        0.04419417382415922f);

    softmax_rows<<<32768, 256>>>(att_);

    // value = att@v  (A rm [2048,1024], B [1024,512] per batch)
    tc_gemm<0,0,0><<<dim3(4, 16, 16), th>>>(att_, v_, nullptr, val_,
        1024, 1024, 512, 512, 2048LL * 1024, 1024LL * 512, 2048LL * 512, 1.f);

    // out^T = Wmel^T @ val^T + bmel, with fused permute
    // (A k-major [512,1280] shared, B^T = val [2048,512] per batch, cols = t)
    tc_gemm<1,1,2><<<dim3(16, 10, 16), th>>>(Wmel, val_, bmel, out,
        512, 1280, 512, 2048, 0, 2048LL * 512, 0, 1.f);
}

// round 7
// speedup vs baseline: 3.6115x; 1.0840x over previous
#include <cuda_runtime.h>
#include <cstdint>

// ---------------- scratch (device globals; no allocation allowed) ------------
__device__ float g_k  [16LL * 1024 * 512];   //  33.5 MB
__device__ float g_v  [16LL * 1024 * 512];   //  33.5 MB
__device__ float g_q  [16LL * 2048 * 512];   //  67 MB
__device__ float g_att[16LL * 2048 * 1024];  // 134 MB
__device__ float g_val[16LL * 2048 * 512];   //  67 MB
__device__ int   g_len[16];

// -------- lengths dtype sniffing (reference says int64; JAX x64-off -> int32)
__global__ void normalize_lengths(const void* __restrict__ lp)
{
    const long long* l8 = (const long long*)lp;
    const int*       l4 = (const int*)lp;
    bool ok64 = true;
    for (int i = 0; i < 8; ++i) {
        long long v = l8[i];
        if (v < 1 || v > 1024) ok64 = false;
    }
    if (ok64) {
        for (int i = 0; i < 16; ++i) g_len[i] = (int)l8[i];
    } else {
        for (int i = 0; i < 16; ++i) g_len[i] = l4[i];
    }
}

// ---------------------------------------------------------------------------
// tf32 helpers
__device__ __forceinline__ unsigned f2tf(float x) {
    unsigned u;
    asm("cvt.rna.tf32.f32 %0, %1;" : "=r"(u) : "f"(x));
    return u;
}

__device__ __forceinline__ void mma8(float* c, const unsigned* a,
                                     unsigned b0, unsigned b1) {
    asm volatile(
        "mma.sync.aligned.m16n8k8.row.col.f32.tf32.tf32.f32 "
        "{%0,%1,%2,%3},{%4,%5,%6,%7},{%8,%9},{%0,%1,%2,%3};"
        : "+f"(c[0]), "+f"(c[1]), "+f"(c[2]), "+f"(c[3])
        : "r"(a[0]), "r"(a[1]), "r"(a[2]), "r"(a[3]), "r"(b0), "r"(b1));
}

// ---------------------------------------------------------------------------
// Unified tf32 tensor-core GEMM, 128x128x16 CTA tiles, 128 threads
// (4 warps 2m x 2n), warp tile 64x64, m16n8k8. Double-buffered smem,
// LDG register prefetch, 2 CTAs/SM.
//
// AT=0: A row-major [M,K]  (m rows, k contig)  -> smem As[m][20]
// AT=1: A k-major  [K,M]   (k rows, m contig)  -> smem As[k][136]
// BT=0: B [K,N]            (k rows, n contig)  -> smem Bs[k][136]
// BT=1: B^T [N,K]          (n rows, k contig)  -> smem Bs[n][20]
// EPI=0: C = alpha*(A@B) + bias[col] (bias optional), row-major ldc
// EPI=2: mel permute: rows are mel indices, cols are t
template<int AT, int BT, int EPI>
__global__ __launch_bounds__(128, 2) void tc_gemm(
    const float* __restrict__ A, const float* __restrict__ Bm,
    const float* __restrict__ bias, float* __restrict__ C,
    int K, int lda, int ldb, int ldc,
    long long sA, long long sB, long long sC, float alpha)
{
    constexpr int ASZ = AT ? 16 * 136 : 128 * 20;
    constexpr int BSZ = BT ? 128 * 20 : 16 * 136;
    __shared__ unsigned smA[2][ASZ];
    __shared__ unsigned smB[2][BSZ];

    A  += blockIdx.z * sA;
    Bm += blockIdx.z * sB;
    const int tid  = threadIdx.x;
    const int lane = tid & 31, warp = tid >> 5;
    const int g  = lane >> 2, tg = lane & 3;
    const int wm = warp & 1,  wn = warp >> 1;          // 2 x 2 warps
    const int r0 = blockIdx.y * 128, c0 = blockIdx.x * 128;

    const float* aptr[4]; unsigned adst[4];
    const float* bptr[4]; unsigned bdst[4];
    #pragma unroll
    for (int r = 0; r < 4; ++r) {
        int i = tid + 128 * r;                          // 0..511, 4 elems each
        if (!AT) { int m = i >> 2, kq = (i & 3) * 4;
                   aptr[r] = A + (long long)(r0 + m) * lda + kq;
                   adst[r] = m * 20 + kq; }
        else     { int k = i >> 5, m4 = (i & 31) * 4;
                   aptr[r] = A + (long long)k * lda + r0 + m4;
                   adst[r] = k * 136 + m4; }
        if (!BT) { int k = i >> 5, n4 = (i & 31) * 4;
                   bptr[r] = Bm + (long long)k * ldb + c0 + n4;
                   bdst[r] = k * 136 + n4; }
        else     { int n = i >> 2, kq = (i & 3) * 4;
                   bptr[r] = Bm + (long long)(c0 + n) * ldb + kq;
                   bdst[r] = n * 20 + kq; }
    }
    const long long adv_a = AT ? 16LL * lda : 16LL;
    const long long adv_b = BT ? 16LL : 16LL * ldb;

    float acc[4][8][4] = {};
    const int nIter = K >> 4;

    float4 pa[4], pb[4];
    #pragma unroll
    for (int r = 0; r < 4; ++r) {
        pa[r] = *(const float4*)aptr[r];
        pb[r] = *(const float4*)bptr[r];
    }

    int buf = 0;
    for (int it = 0; it < nIter; ++it) {
        #pragma unroll
        for (int r = 0; r < 4; ++r) {
            uint4 ua; ua.x = f2tf(pa[r].x); ua.y = f2tf(pa[r].y);
                      ua.z = f2tf(pa[r].z); ua.w = f2tf(pa[r].w);
            *(uint4*)&smA[buf][adst[r]] = ua;
            uint4 ub; ub.x = f2tf(pb[r].x); ub.y = f2tf(pb[r].y);
                      ub.z = f2tf(pb[r].z); ub.w = f2tf(pb[r].w);
            *(uint4*)&smB[buf][bdst[r]] = ub;
        }
        __syncthreads();
        if (it + 1 < nIter) {
            #pragma unroll
            for (int r = 0; r < 4; ++r) {
                aptr[r] += adv_a; bptr[r] += adv_b;
                pa[r] = *(const float4*)aptr[r];
                pb[r] = *(const float4*)bptr[r];
            }
        }
        const unsigned* As = smA[buf];
        const unsigned* Bs = smB[buf];
        #pragma unroll
        for (int kk = 0; kk < 16; kk += 8) {
            unsigned af[4][4];
            const int k = kk + tg;
            #pragma unroll
            for (int mi = 0; mi < 4; ++mi) {
                int m = wm * 64 + mi * 16 + g;
                if (!AT) {
                    af[mi][0] = As[m * 20 + k];
                    af[mi][1] = As[(m + 8) * 20 + k];
                    af[mi][2] = As[m * 20 + k + 4];
                    af[mi][3] = As[(m + 8) * 20 + k + 4];
                } else {
                    af[mi][0] = As[k * 136 + m];
                    af[mi][1] = As[k * 136 + m + 8];
                    af[mi][2] = As[(k + 4) * 136 + m];
                    af[mi][3] = As[(k + 4) * 136 + m + 8];
                }
            }
            #pragma unroll
            for (int ni = 0; ni < 8; ++ni) {
                int n = wn * 64 + ni * 8 + g;
                unsigned b0, b1;
                if (!BT) { b0 = Bs[k * 136 + n]; b1 = Bs[(k + 4) * 136 + n]; }
                else     { b0 = Bs[n * 20 + k];  b1 = Bs[n * 20 + k + 4]; }
                #pragma unroll
                for (int mi = 0; mi < 4; ++mi)
                    mma8(acc[mi][ni], af[mi], b0, b1);
            }
        }
        buf ^= 1;
    }

    if (EPI == 2) {
        const int b = blockIdx.z;
        #pragma unroll
        for (int mi = 0; mi < 4; ++mi) {
            int row = r0 + wm * 64 + mi * 16 + g;
            #pragma unroll
            for (int rr = 0; rr < 2; ++rr) {
                int mel = row + rr * 8;
                float bb = bias[mel];
                float* op = C + ((long long)(b * 64 + (mel & 63)) * 20 + (mel >> 6)) * 2048;
                #pragma unroll
                for (int ni = 0; ni < 8; ++ni) {
                    int t = c0 + wn * 64 + ni * 8 + 2 * tg;
                    float2 v;
                    v.x = acc[mi][ni][rr * 2 + 0] + bb;
                    v.y = acc[mi][ni][rr * 2 + 1] + bb;
                    *(float2*)(op + t) = v;
                }
            }
        }
    } else {
        C += blockIdx.z * sC;
        #pragma unroll
        for (int mi = 0; mi < 4; ++mi) {
            int row = r0 + wm * 64 + mi * 16 + g;
            #pragma unroll
            for (int ni = 0; ni < 8; ++ni) {
                int col = c0 + wn * 64 + ni * 8 + 2 * tg;
                float b0v = bias ? bias[col] : 0.f;
                float b1v = bias ? bias[col + 1] : 0.f;
                float2 v0, v1;
                v0.x = alpha * acc[mi][ni][0] + b0v;
                v0.y = alpha * acc[mi][ni][1] + b1v;
                v1.x = alpha * acc[mi][ni][2] + b0v;
                v1.y = alpha * acc[mi][ni][3] + b1v;
                *(float2*)(C + (long long)row * ldc + col)       = v0;
                *(float2*)(C + (long long)(row + 8) * ldc + col) = v1;
            }
        }
    }
}

// -------- masked softmax over S=1024 per (b,t) row ---------------------------
__global__ __launch_bounds__(256) void softmax_rows(float* __restrict__ att)
{
    const int row = blockIdx.x;
    const int b = row >> 11;
    float* p = att + (long long)row * 1024;
    const int len = g_len[b];
    const int tid = threadIdx.x;
    const int s0 = tid * 4;
    float4 v = ((const float4*)p)[tid];
    float vals[4] = {v.x, v.y, v.z, v.w};
    float mx = -1e30f;
    #pragma unroll
    for (int u = 0; u < 4; ++u)
        if (s0 + u < len && vals[u] > mx) mx = vals[u];
    __shared__ float red[8];
    #pragma unroll
    for (int off = 16; off > 0; off >>= 1)
        mx = fmaxf(mx, __shfl_xor_sync(0xffffffffu, mx, off));
    if ((tid & 31) == 0) red[tid >> 5] = mx;
    __syncthreads();
    mx = red[0];
    #pragma unroll
    for (int i = 1; i < 8; ++i) mx = fmaxf(mx, red[i]);
    __syncthreads();
    float sum = 0.f;
    #pragma unroll
    for (int u = 0; u < 4; ++u) {
        float e = (s0 + u < len) ? __expf(vals[u] - mx) : 0.f;
        vals[u] = e; sum += e;
    }
    #pragma unroll
    for (int off = 16; off > 0; off >>= 1)
        sum += __shfl_xor_sync(0xffffffffu, sum, off);
    if ((tid & 31) == 0) red[tid >> 5] = sum;
    __syncthreads();
    sum = 0.f;
    #pragma unroll
    for (int i = 0; i < 8; ++i) sum += red[i];
    const float inv = 1.f / sum;
    v.x = vals[0] * inv; v.y = vals[1] * inv;
    v.z = vals[2] * inv; v.w = vals[3] * inv;
    ((float4*)p)[tid] = v;
}

// ---------------------------------------------------------------------------
extern "C" void kernel_launch(void* const* d_in, const int* in_sizes, int n_in,
                              void* d_out, int out_size)
{
    const float* ph      = (const float*)d_in[0];   // [16,1024,512]
    const float* g       = (const float*)d_in[1];   // [16,2560,2048] (c*f, t)
    const void*  lengths = d_in[2];
    const float* Wk      = (const float*)d_in[3];
    const float* bk      = (const float*)d_in[4];
    const float* Wv      = (const float*)d_in[5];
    const float* bv      = (const float*)d_in[6];
    const float* Wq      = (const float*)d_in[7];
    const float* bq      = (const float*)d_in[8];
    const float* Wmel    = (const float*)d_in[9];
    const float* bmel    = (const float*)d_in[10];
    float* out = (float*)d_out;

    float *k_, *v_, *q_, *att_, *val_;
    cudaGetSymbolAddress((void**)&k_,   g_k);
    cudaGetSymbolAddress((void**)&v_,   g_v);
    cudaGetSymbolAddress((void**)&q_,   g_q);
    cudaGetSymbolAddress((void**)&att_, g_att);
    cudaGetSymbolAddress((void**)&val_, g_val);

    const dim3 th(128);

    normalize_lengths<<<1, 1>>>(lengths);

    // k = ph@Wk + bk ; v = ph@Wv + bv   (A rm [16384,512], B [512,512])
    tc_gemm<0,0,0><<<dim3(4, 128, 1), th>>>(ph, Wk, bk, k_,
        512, 512, 512, 512, 0, 0, 0, 1.f);
    tc_gemm<0,0,0><<<dim3(4, 128, 1), th>>>(ph, Wv, bv, v_,
        512, 512, 512, 512, 0, 0, 0, 1.f);

    // q = g^T@Wq + bq  (A k-major [2560,2048] per batch, B [2560,512])
    tc_gemm<1,0,0><<<dim3(4, 16, 16), th>>>(g, Wq, bq, q_,
        2560, 2048, 512, 512, 2560LL * 2048, 0, 2048LL * 512, 1.f);

    // att = scale * q@k^T  (A rm [2048,512], B^T [1024,512] per batch)
    tc_gemm<0,1,0><<<dim3(8, 16, 16), th>>>(q_, k_, nullptr, att_,
        512, 512, 512, 1024, 2048LL * 512, 1024LL * 512, 2048LL * 1024,
        0.04419417382415922f);

    softmax_rows<<<32768, 256>>>(att_);

    // value = att@v  (A rm [2048,1024], B [1024,512] per batch)
    tc_gemm<0,0,0><<<dim3(4, 16, 16), th>>>(att_, v_, nullptr, val_,
        1024, 1024, 512, 512, 2048LL * 1024, 1024LL * 512, 2048LL * 512, 1.f);

    // out^T = Wmel^T @ val^T + bmel, with fused permute
    // (A k-major [512,1280] shared, B^T = val [2048,512] per batch, cols = t)
    tc_gemm<1,1,2><<<dim3(16, 10, 16), th>>>(Wmel, val_, bmel, out,
        512, 1280, 512, 2048, 0, 2048LL * 512, 0, 1.f);
}